// round 13
// baseline (speedup 1.0000x reference)
#include <cuda_runtime.h>
#include <cuda_fp16.h>
#include <math.h>
#include <stdint.h>

#define FH 100
#define FW 150
#define CIN 1024
#define CMID 512
#define NPIX 15000
#define NANCH 135000
#define PRE_NMS 6000
#define POST_NMS 300
#define NBLK 94          /* ceil(6000/64) */
#define HBITS 18
#define HSIZE (1 << HBITS)
#define CAND_CAP 8192
#define NEG_BIG -1000000000.0f

/* GEMM config: M=15104(pad), N=512, K=9216. CTA 128x128, K-chunk 32. */
#define TM 128
#define TN 128
#define KC 32
#define KTOT 9216
#define NC (KTOT / KC)          /* 288 */
#define ASTR 40                 /* halves per row (80 B, conflict-free LDS) */
#define AHI_O 0
#define ALO_O 5120
#define BHI_O 10240
#define BLO_O 15360
#define STAGE_H 20480           /* halves per stage */
#define SMEM_CONV_TOTAL (2 * STAGE_H * 2)   /* 81920 bytes */
#define LO_SCALE 2048.0f
#define LO_INV (1.0f / 2048.0f)

/* ------------------- static device scratch (no allocs allowed) ------------ */
__device__ __half g_Ahi[(size_t)NPIX * CIN];
__device__ __half g_Alo[(size_t)NPIX * CIN];
__device__ __half g_Bhi[(size_t)CMID * KTOT];   /* [n][k] */
__device__ __half g_Blo[(size_t)CMID * KTOT];
__device__ float g_rpn[(size_t)NPIX * CMID];
__device__ float g_scores[NANCH];
__device__ float g_boxes[NANCH * 4];
__device__ unsigned int g_hist[HSIZE];
__device__ int g_cand_cnt;
__device__ int g_thresh_bin;
__device__ unsigned long long g_cand[CAND_CAP];
__device__ float g_top_scores[PRE_NMS];
__device__ float g_top_boxes[PRE_NMS * 4];
__device__ unsigned long long g_mask[(size_t)PRE_NMS * NBLK];

__constant__ float c_anch[9][4] = {
    {-84.f, -40.f, 99.f, 55.f},   {-176.f, -88.f, 191.f, 103.f},
    {-360.f, -184.f, 375.f, 199.f},
    {-56.f, -56.f, 71.f, 71.f},   {-120.f, -120.f, 135.f, 135.f},
    {-248.f, -248.f, 263.f, 263.f},
    {-36.f, -80.f, 51.f, 95.f},   {-80.f, -168.f, 95.f, 183.f},
    {-168.f, -344.f, 183.f, 359.f}};

__device__ __forceinline__ unsigned fkey(float f) {
    unsigned u = __float_as_uint(f);
    return (u & 0x80000000u) ? ~u : (u | 0x80000000u);
}
#define MMA(acc_, a_, b0_, b1_)                                               \
    asm volatile(                                                             \
        "mma.sync.aligned.m16n8k16.row.col.f32.f16.f16.f32 "                  \
        "{%0,%1,%2,%3}, {%4,%5,%6,%7}, {%8,%9}, {%0,%1,%2,%3};"               \
        : "+f"((acc_)[0]), "+f"((acc_)[1]), "+f"((acc_)[2]), "+f"((acc_)[3])  \
        : "r"((a_)[0]), "r"((a_)[1]), "r"((a_)[2]), "r"((a_)[3]),             \
          "r"(b0_), "r"(b1_))

/* ------------------- pre-convert feat -> fp16 hi/lo ----------------------- */
__global__ __launch_bounds__(256) void convert_feat_kernel(
    const float* __restrict__ feat) {
    size_t i = ((size_t)blockIdx.x * 256 + threadIdx.x) * 4;
    float4 v = *(const float4*)(feat + i);
    __half hx = __float2half_rn(v.x), hy = __float2half_rn(v.y);
    __half hz = __float2half_rn(v.z), hw = __float2half_rn(v.w);
    *(__half2*)(g_Ahi + i) = __halves2half2(hx, hy);
    *(__half2*)(g_Ahi + i + 2) = __halves2half2(hz, hw);
    *(__half2*)(g_Alo + i) = __halves2half2(
        __float2half_rn((v.x - __half2float(hx)) * LO_SCALE),
        __float2half_rn((v.y - __half2float(hy)) * LO_SCALE));
    *(__half2*)(g_Alo + i + 2) = __halves2half2(
        __float2half_rn((v.z - __half2float(hz)) * LO_SCALE),
        __float2half_rn((v.w - __half2float(hw)) * LO_SCALE));
}

/* ------------------- weight transpose+split: [9216,512] -> [512,9216] ----- */
__global__ __launch_bounds__(256) void convert_w_kernel(const float* __restrict__ W) {
    __shared__ float t[32][33];
    const int kb = blockIdx.x * 32, cb = blockIdx.y * 32;
    const int tx = threadIdx.x, ty = threadIdx.y;   /* 32 x 8 */
#pragma unroll
    for (int r = ty; r < 32; r += 8)
        t[r][tx] = W[(size_t)(kb + r) * CMID + cb + tx];
    __syncthreads();
#pragma unroll
    for (int r = ty; r < 32; r += 8) {
        float v = t[tx][r];
        __half h = __float2half_rn(v);
        size_t o = (size_t)(cb + r) * KTOT + kb + tx;
        g_Bhi[o] = h;
        g_Blo[o] = __float2half_rn((v - __half2float(h)) * LO_SCALE);
    }
}

/* ------------------- conv as HMMA fp16-split GEMM ------------------------- */
/* D = A_hi*B_hi + (A_hi*B_lo' + A_lo'*B_hi) * 2^-11, lo' = (x-hi)*2^11.      */
/* CTA 128x128, warp tile 32x64. Single barrier per chunk.                    */
__global__ __launch_bounds__(256, 1) void conv_mma_kernel(
    const float* __restrict__ bias) {
    extern __shared__ __half smh[];
    const int tid = threadIdx.x;
    const int wid = tid >> 5, lane = tid & 31;
    const int m0 = blockIdx.x * TM;   /* 118 m-tiles */
    const int n0 = blockIdx.y * TN;   /* 4 n-tiles */
    const int wm = wid >> 1, wn = wid & 1;   /* 4x2 warps of 32x64 */
    const int r = lane >> 2, cp2 = (lane & 3) * 2;

    /* A loader: 1 row, 32 halves (2 uint4 hi + 2 lo) per thread */
    const int arow = tid >> 1;
    const int c16a = (tid & 1) * 16;
    const int pA = m0 + arow;
    const int apy = pA / FW;
    const int apx = pA - apy * FW;
    const int aok = (pA < NPIX);
    /* B loader: same geometry */
    const int brow = tid >> 1;
    const int c16b = (tid & 1) * 16;
    const __half* bsrc_hi = g_Bhi + (size_t)(n0 + brow) * KTOT + c16b;
    const __half* bsrc_lo = g_Blo + (size_t)(n0 + brow) * KTOT + c16b;

    float acc0[2][8][4], acc1[2][8][4];
#pragma unroll
    for (int i = 0; i < 2; i++)
#pragma unroll
        for (int j = 0; j < 8; j++)
#pragma unroll
            for (int k = 0; k < 4; k++) { acc0[i][j][k] = 0.f; acc1[i][j][k] = 0.f; }

    uint4 hA[2], lA[2], hB[2], lB[2];

#define LOAD_CHUNK(c_)                                                        \
    do {                                                                      \
        const int tap_ = (c_) >> 5;                                           \
        const int ci0_ = ((c_) & 31) * KC;                                    \
        const int dy_ = tap_ / 3 - 1, dx_ = tap_ % 3 - 1;                     \
        const int yy = apy + dy_, xx = apx + dx_;                             \
        if (aok && (unsigned)yy < FH && (unsigned)xx < FW) {                  \
            const __half* s =                                                 \
                g_Ahi + (((size_t)(yy * FW + xx)) << 10) + ci0_ + c16a;       \
            const __half* s2 =                                                \
                g_Alo + (((size_t)(yy * FW + xx)) << 10) + ci0_ + c16a;       \
            hA[0] = *(const uint4*)s;                                         \
            hA[1] = *(const uint4*)(s + 8);                                   \
            lA[0] = *(const uint4*)s2;                                        \
            lA[1] = *(const uint4*)(s2 + 8);                                  \
        } else {                                                              \
            hA[0] = make_uint4(0, 0, 0, 0); hA[1] = hA[0];                    \
            lA[0] = hA[0]; lA[1] = hA[0];                                     \
        }                                                                     \
        hB[0] = *(const uint4*)(bsrc_hi + (size_t)(c_) * KC);                 \
        hB[1] = *(const uint4*)(bsrc_hi + (size_t)(c_) * KC + 8);             \
        lB[0] = *(const uint4*)(bsrc_lo + (size_t)(c_) * KC);                 \
        lB[1] = *(const uint4*)(bsrc_lo + (size_t)(c_) * KC + 8);             \
    } while (0)

#define STORE_STAGE(buf_)                                                     \
    do {                                                                      \
        __half* bse = smh + (buf_) * STAGE_H;                                 \
        *(uint4*)(bse + AHI_O + arow * ASTR + c16a) = hA[0];                  \
        *(uint4*)(bse + AHI_O + arow * ASTR + c16a + 8) = hA[1];              \
        *(uint4*)(bse + ALO_O + arow * ASTR + c16a) = lA[0];                  \
        *(uint4*)(bse + ALO_O + arow * ASTR + c16a + 8) = lA[1];              \
        *(uint4*)(bse + BHI_O + brow * ASTR + c16b) = hB[0];                  \
        *(uint4*)(bse + BHI_O + brow * ASTR + c16b + 8) = hB[1];              \
        *(uint4*)(bse + BLO_O + brow * ASTR + c16b) = lB[0];                  \
        *(uint4*)(bse + BLO_O + brow * ASTR + c16b + 8) = lB[1];              \
    } while (0)

    LOAD_CHUNK(0);
    STORE_STAGE(0);
    LOAD_CHUNK(1);
    __syncthreads();

    for (int c = 0; c < NC; c++) {
        const int buf = c & 1;
        /* stores for chunk c+1 go to buf^1: all readers of buf^1 finished at
           the barrier that ended iteration c-1; compute below reads buf. */
        if (c + 1 < NC) STORE_STAGE(buf ^ 1);
        if (c + 2 < NC) LOAD_CHUNK(c + 2);

        const __half* bse = smh + buf * STAGE_H;
#pragma unroll
        for (int ks = 0; ks < 2; ks++) {
            const int k0 = ks * 16;
            uint32_t ah[2][4], al[2][4];
#pragma unroll
            for (int mt = 0; mt < 2; mt++) {
                const __half* ap = bse + AHI_O + (wm * 32 + mt * 16) * ASTR + k0;
                ah[mt][0] = *(const uint32_t*)(ap + r * ASTR + cp2);
                ah[mt][1] = *(const uint32_t*)(ap + (r + 8) * ASTR + cp2);
                ah[mt][2] = *(const uint32_t*)(ap + r * ASTR + cp2 + 8);
                ah[mt][3] = *(const uint32_t*)(ap + (r + 8) * ASTR + cp2 + 8);
                const __half* ap2 = ap + (ALO_O - AHI_O);
                al[mt][0] = *(const uint32_t*)(ap2 + r * ASTR + cp2);
                al[mt][1] = *(const uint32_t*)(ap2 + (r + 8) * ASTR + cp2);
                al[mt][2] = *(const uint32_t*)(ap2 + r * ASTR + cp2 + 8);
                al[mt][3] = *(const uint32_t*)(ap2 + (r + 8) * ASTR + cp2 + 8);
            }
#pragma unroll
            for (int nt = 0; nt < 8; nt++) {
                const __half* bp = bse + BHI_O + (wn * 64 + nt * 8) * ASTR + k0;
                uint32_t bh0 = *(const uint32_t*)(bp + r * ASTR + cp2);
                uint32_t bh1 = *(const uint32_t*)(bp + r * ASTR + cp2 + 8);
                const __half* bp2 = bp + (BLO_O - BHI_O);
                uint32_t bl0 = *(const uint32_t*)(bp2 + r * ASTR + cp2);
                uint32_t bl1 = *(const uint32_t*)(bp2 + r * ASTR + cp2 + 8);
#pragma unroll
                for (int mt = 0; mt < 2; mt++) {
                    MMA(acc0[mt][nt], ah[mt], bh0, bh1);
                    MMA(acc1[mt][nt], ah[mt], bl0, bl1);
                    MMA(acc1[mt][nt], al[mt], bh0, bh1);
                }
            }
        }
        __syncthreads();
    }

    /* epilogue: combine, bias, relu, store */
#pragma unroll
    for (int mt = 0; mt < 2; mt++) {
#pragma unroll
        for (int nt = 0; nt < 8; nt++) {
            const int n = n0 + wn * 64 + nt * 8 + cp2;
            const float b0v = bias[n], b1v = bias[n + 1];
            const int mA = m0 + wm * 32 + mt * 16 + r;
            const int mB = mA + 8;
            float v0 = acc0[mt][nt][0] + acc1[mt][nt][0] * LO_INV + b0v;
            float v1 = acc0[mt][nt][1] + acc1[mt][nt][1] * LO_INV + b1v;
            float v2 = acc0[mt][nt][2] + acc1[mt][nt][2] * LO_INV + b0v;
            float v3 = acc0[mt][nt][3] + acc1[mt][nt][3] * LO_INV + b1v;
            if (mA < NPIX) {
                g_rpn[(size_t)mA * CMID + n] = fmaxf(v0, 0.f);
                g_rpn[(size_t)mA * CMID + n + 1] = fmaxf(v1, 0.f);
            }
            if (mB < NPIX) {
                g_rpn[(size_t)mB * CMID + n] = fmaxf(v2, 0.f);
                g_rpn[(size_t)mB * CMID + n + 1] = fmaxf(v3, 0.f);
            }
        }
    }
}

/* ------------------- 1x1 heads + softmax + box decode --------------------- */
__global__ __launch_bounds__(64) void head_decode_kernel(
    const float* __restrict__ Ws, const float* __restrict__ bs,
    const float* __restrict__ Wb, const float* __restrict__ bb,
    const int* __restrict__ img) {
    const int ppix = blockIdx.x;
    __shared__ float s[CMID];
    __shared__ float outv[54];
    const int t = threadIdx.x;

    for (int i = t; i < CMID; i += 64) s[i] = g_rpn[(size_t)ppix * CMID + i];
    __syncthreads();

    if (t < 54) {
        const bool isc = (t < 18);
        const float* Wp = isc ? Ws : Wb;
        const int co = isc ? t : (t - 18);
        const int stride = isc ? 18 : 36;
        float a0 = 0.f, a1 = 0.f, a2 = 0.f, a3 = 0.f;
        for (int c = 0; c < CMID; c += 4) {
            a0 += s[c + 0] * Wp[(c + 0) * stride + co];
            a1 += s[c + 1] * Wp[(c + 1) * stride + co];
            a2 += s[c + 2] * Wp[(c + 2) * stride + co];
            a3 += s[c + 3] * Wp[(c + 3) * stride + co];
        }
        outv[t] = (isc ? bs[t] : bb[t - 18]) + ((a0 + a1) + (a2 + a3));
    }
    __syncthreads();

    if (t < 9) {
        const float l0 = outv[t * 2 + 0], l1 = outv[t * 2 + 1];
        const float mx = fmaxf(l0, l1);
        const float e0 = expf(l0 - mx), e1 = expf(l1 - mx);
        float fg = e1 / (e0 + e1);

        const float dx = outv[18 + t * 4 + 0];
        const float dy = outv[18 + t * 4 + 1];
        const float dw = outv[18 + t * 4 + 2];
        const float dh = outv[18 + t * 4 + 3];

        const int y = ppix / FW, x = ppix % FW;
        const float sx = (float)(x * 16), sy = (float)(y * 16);
        const float ax1 = sx + c_anch[t][0];
        const float ay1 = sy + c_anch[t][1];
        const float ax2 = sx + c_anch[t][2];
        const float ay2 = sy + c_anch[t][3];
        const float aw = ax2 - ax1 + 1.f;
        const float ah = ay2 - ay1 + 1.f;
        const float acx = ax1 + 0.5f * aw;
        const float acy = ay1 + 0.5f * ah;
        const float pcx = dx * aw + acx;
        const float pcy = dy * ah + acy;
        const float pw = expf(dw) * aw;
        const float ph = expf(dh) * ah;
        const float imh = (float)img[0];
        const float imw = (float)img[1];
        float x1 = fminf(fmaxf(pcx - 0.5f * pw, 0.f), imw - 1.f);
        float y1 = fminf(fmaxf(pcy - 0.5f * ph, 0.f), imh - 1.f);
        float x2 = fminf(fmaxf(pcx + 0.5f * pw, 0.f), imw - 1.f);
        float y2 = fminf(fmaxf(pcy + 0.5f * ph, 0.f), imh - 1.f);
        const float bw = x2 - x1 + 1.f;
        const float bh = y2 - y1 + 1.f;
        if (!(bw >= 16.f && bh >= 16.f)) fg = NEG_BIG;

        const int idx = ppix * 9 + t;
        g_scores[idx] = fg;
        g_boxes[idx * 4 + 0] = x1;
        g_boxes[idx * 4 + 1] = y1;
        g_boxes[idx * 4 + 2] = x2;
        g_boxes[idx * 4 + 3] = y2;
    }
}

/* ------------------- top-6000 selection ----------------------------------- */
__global__ void zero_aux_kernel() {
    int i = blockIdx.x * blockDim.x + threadIdx.x;
    if (i < HSIZE) g_hist[i] = 0;
    if (i < CAND_CAP) g_cand[i] = 0ull;
    if (i == 0) g_cand_cnt = 0;
}

__global__ void hist_kernel() {
    int i = blockIdx.x * blockDim.x + threadIdx.x;
    if (i < NANCH) {
        unsigned key = fkey(g_scores[i]);
        atomicAdd(&g_hist[key >> (32 - HBITS)], 1u);
    }
}

__global__ void find_thresh_kernel() {
    __shared__ unsigned csum[1024];
    const int t = threadIdx.x;
    const int chunk = HSIZE / 1024; /* 256 */
    unsigned s = 0;
    const int base = t * chunk;
    for (int i = 0; i < chunk; i++) s += g_hist[base + i];
    csum[t] = s;
    __syncthreads();
    if (t == 0) {
        unsigned cum = 0;
        int c = 1023;
        for (; c >= 0; c--) {
            if (cum + csum[c] >= (unsigned)PRE_NMS) break;
            cum += csum[c];
        }
        int B = 0;
        if (c >= 0) {
            for (int b = c * chunk + chunk - 1; b >= c * chunk; b--) {
                cum += g_hist[b];
                if (cum >= (unsigned)PRE_NMS) { B = b; break; }
            }
        }
        g_thresh_bin = B;
    }
}

__global__ void compact_kernel() {
    int i = blockIdx.x * blockDim.x + threadIdx.x;
    if (i < NANCH) {
        unsigned key = fkey(g_scores[i]);
        if ((int)(key >> (32 - HBITS)) >= g_thresh_bin) {
            int pos = atomicAdd(&g_cand_cnt, 1);
            if (pos < CAND_CAP)
                g_cand[pos] = ((unsigned long long)key << 32) |
                              (unsigned)(~(unsigned)i);
        }
    }
}

/* single-block bitonic sort of 8192 64-bit keys, descending.
   key = flip(score)<<32 | ~idx  ->  stable top-k identical to lax.top_k. */
__global__ void sort_kernel() {
    extern __shared__ unsigned long long sk[];
    const int t = threadIdx.x;
    for (int i = t; i < CAND_CAP; i += 1024) sk[i] = g_cand[i];
    __syncthreads();
    for (int k = 2; k <= CAND_CAP; k <<= 1) {
        for (int j = k >> 1; j > 0; j >>= 1) {
            for (int i = t; i < CAND_CAP; i += 1024) {
                int l = i ^ j;
                if (l > i) {
                    bool desc = ((i & k) == 0);
                    unsigned long long a = sk[i], b = sk[l];
                    if ((a < b) == desc) { sk[i] = b; sk[l] = a; }
                }
            }
            __syncthreads();
        }
    }
    for (int i = t; i < PRE_NMS; i += 1024) {
        unsigned long long key = sk[i];
        if (key == 0ull) {
            g_top_scores[i] = -2e9f;
            g_top_boxes[i * 4 + 0] = 0.f;
            g_top_boxes[i * 4 + 1] = 0.f;
            g_top_boxes[i * 4 + 2] = 0.f;
            g_top_boxes[i * 4 + 3] = 0.f;
            continue;
        }
        unsigned idx = ~(unsigned)(key & 0xFFFFFFFFull);
        g_top_scores[i] = g_scores[idx];
        g_top_boxes[i * 4 + 0] = g_boxes[idx * 4 + 0];
        g_top_boxes[i * 4 + 1] = g_boxes[idx * 4 + 1];
        g_top_boxes[i * 4 + 2] = g_boxes[idx * 4 + 2];
        g_top_boxes[i * 4 + 3] = g_boxes[idx * 4 + 3];
    }
}

/* ------------------- NMS ---------------------------------------------------*/
__global__ __launch_bounds__(64) void nms_mask_kernel() {
    const int cb = blockIdx.x, rb = blockIdx.y;
    __shared__ float4 cbox[64];
    const int t = threadIdx.x;
    const int cj = cb * 64 + t;
    if (cj < PRE_NMS) cbox[t] = *(const float4*)&g_top_boxes[cj * 4];
    __syncthreads();
    const int i = rb * 64 + t;
    if (i >= PRE_NMS) return;
    const float4 r = *(const float4*)&g_top_boxes[i * 4];
    const float ra = (r.z - r.x + 1.f) * (r.w - r.y + 1.f);
    const int cc = min(64, PRE_NMS - cb * 64);
    unsigned long long m = 0ull;
    for (int jj = 0; jj < cc; jj++) {
        const float4 c = cbox[jj];
        float iw = fminf(r.z, c.z) - fmaxf(r.x, c.x) + 1.f;
        float ih = fminf(r.w, c.w) - fmaxf(r.y, c.y) + 1.f;
        iw = fmaxf(iw, 0.f);
        ih = fmaxf(ih, 0.f);
        const float inter = iw * ih;
        const float ca = (c.z - c.x + 1.f) * (c.w - c.y + 1.f);
        const float iou = inter / (ra + ca - inter);
        if (iou > 0.7f) m |= (1ull << jj);
    }
    g_mask[(size_t)i * NBLK + cb] = m;
}

__global__ __launch_bounds__(128) void nms_reduce_kernel(float* __restrict__ out) {
    __shared__ unsigned long long remv[NBLK];
    __shared__ int cnt;
    const int t = threadIdx.x;
    if (t < NBLK) remv[t] = 0ull;
    if (t == 0) cnt = 0;
    for (int i = t; i < POST_NMS * 4; i += 128) out[i] = 0.f;
    __syncthreads();
    for (int i = 0; i < PRE_NMS; i++) {
        const bool keep = !((remv[i >> 6] >> (i & 63)) & 1ull);
        if (keep) {
            if (t < NBLK) remv[t] |= g_mask[(size_t)i * NBLK + t];
            if (t == 0 && g_top_scores[i] > -100000000.0f) {
                const int c = cnt;
                out[c * 4 + 0] = g_top_boxes[i * 4 + 0];
                out[c * 4 + 1] = g_top_boxes[i * 4 + 1];
                out[c * 4 + 2] = g_top_boxes[i * 4 + 2];
                out[c * 4 + 3] = g_top_boxes[i * 4 + 3];
                cnt = c + 1;
            }
            __syncthreads();
            if (cnt >= POST_NMS) break;
        }
    }
}

/* ------------------- launch ------------------------------------------------*/
extern "C" void kernel_launch(void* const* d_in, const int* in_sizes, int n_in,
                              void* d_out, int out_size) {
    const float* feat = (const float*)d_in[0];
    const float* Wr   = (const float*)d_in[1];
    const float* br   = (const float*)d_in[2];
    const float* Ws   = (const float*)d_in[3];
    const float* bs   = (const float*)d_in[4];
    const float* Wb   = (const float*)d_in[5];
    const float* bb   = (const float*)d_in[6];
    const int*   img  = (const int*)d_in[7];
    float* out = (float*)d_out;

    convert_feat_kernel<<<NPIX, 256>>>(feat);
    convert_w_kernel<<<dim3(KTOT / 32, CMID / 32), dim3(32, 8)>>>(Wr);

    cudaFuncSetAttribute(conv_mma_kernel,
                         cudaFuncAttributeMaxDynamicSharedMemorySize,
                         SMEM_CONV_TOTAL);
    conv_mma_kernel<<<dim3(118, CMID / TN), 256, SMEM_CONV_TOTAL>>>(br);

    head_decode_kernel<<<NPIX, 64>>>(Ws, bs, Wb, bb, img);
    zero_aux_kernel<<<HSIZE / 256, 256>>>();
    hist_kernel<<<(NANCH + 255) / 256, 256>>>();
    find_thresh_kernel<<<1, 1024>>>();
    compact_kernel<<<(NANCH + 255) / 256, 256>>>();
    cudaFuncSetAttribute(sort_kernel,
                         cudaFuncAttributeMaxDynamicSharedMemorySize, 65536);
    sort_kernel<<<1, 1024, 65536>>>();
    nms_mask_kernel<<<dim3(NBLK, NBLK), 64>>>();
    nms_reduce_kernel<<<1, 128>>>(out);
}

// round 14
// speedup vs baseline: 1.8247x; 1.8247x over previous
#include <cuda_runtime.h>
#include <cuda_fp16.h>
#include <math.h>
#include <stdint.h>

#define FH 100
#define FW 150
#define CIN 1024
#define CMID 512
#define NPIX 15000
#define NANCH 135000
#define PRE_NMS 6000
#define POST_NMS 300
#define NBLK 94          /* ceil(6000/64) */
#define HBITS 18
#define HSIZE (1 << HBITS)
#define CAND_CAP 8192
#define NEG_BIG -1000000000.0f

/* GEMM config: M=15104(pad), N=512, K=9216. CTA 128x64, K-chunk 64. */
#define TM 128
#define TN 64
#define KC 64
#define KTOT 9216
#define NC (KTOT / KC)          /* 144 */
#define ASTR 72                 /* halves per row (144 B, conflict-free) */
#define AHI_O 0
#define ALO_O 9216
#define BHI_O 18432
#define BLO_O 23040
#define STAGE_H 27648           /* halves per stage */
#define SMEM_CONV_TOTAL (2 * STAGE_H * 2)   /* 110592 bytes */
#define LO_SCALE 2048.0f
#define LO_INV (1.0f / 2048.0f)

/* ------------------- static device scratch (no allocs allowed) ------------ */
__device__ __half g_Ahi[(size_t)NPIX * CIN];
__device__ __half g_Alo[(size_t)NPIX * CIN];
__device__ __half g_Bhi[(size_t)CMID * KTOT];   /* [n][k] */
__device__ __half g_Blo[(size_t)CMID * KTOT];
__device__ float g_rpn[(size_t)NPIX * CMID];
__device__ float g_scores[NANCH];
__device__ float g_boxes[NANCH * 4];
__device__ unsigned int g_hist[HSIZE];
__device__ int g_cand_cnt;
__device__ int g_thresh_bin;
__device__ unsigned long long g_cand[CAND_CAP];
__device__ float g_top_scores[PRE_NMS];
__device__ float g_top_boxes[PRE_NMS * 4];
__device__ unsigned long long g_mask[(size_t)PRE_NMS * NBLK];

__constant__ float c_anch[9][4] = {
    {-84.f, -40.f, 99.f, 55.f},   {-176.f, -88.f, 191.f, 103.f},
    {-360.f, -184.f, 375.f, 199.f},
    {-56.f, -56.f, 71.f, 71.f},   {-120.f, -120.f, 135.f, 135.f},
    {-248.f, -248.f, 263.f, 263.f},
    {-36.f, -80.f, 51.f, 95.f},   {-80.f, -168.f, 95.f, 183.f},
    {-168.f, -344.f, 183.f, 359.f}};

__device__ __forceinline__ unsigned fkey(float f) {
    unsigned u = __float_as_uint(f);
    return (u & 0x80000000u) ? ~u : (u | 0x80000000u);
}
__device__ __forceinline__ uint32_t smem_u32(const void* p) {
    uint32_t a;
    asm("{ .reg .u64 t; cvta.to.shared.u64 t, %1; cvt.u32.u64 %0, t; }"
        : "=r"(a) : "l"(p));
    return a;
}
__device__ __forceinline__ void ldsm4(uint32_t* r, uint32_t a) {
    asm volatile("ldmatrix.sync.aligned.m8n8.x4.shared.b16 {%0,%1,%2,%3}, [%4];"
                 : "=r"(r[0]), "=r"(r[1]), "=r"(r[2]), "=r"(r[3]) : "r"(a));
}
#define MMA(acc_, a_, b0_, b1_)                                               \
    asm volatile(                                                             \
        "mma.sync.aligned.m16n8k16.row.col.f32.f16.f16.f32 "                  \
        "{%0,%1,%2,%3}, {%4,%5,%6,%7}, {%8,%9}, {%0,%1,%2,%3};"               \
        : "+f"((acc_)[0]), "+f"((acc_)[1]), "+f"((acc_)[2]), "+f"((acc_)[3])  \
        : "r"((a_)[0]), "r"((a_)[1]), "r"((a_)[2]), "r"((a_)[3]),             \
          "r"(b0_), "r"(b1_))

/* ------------------- pre-convert feat -> fp16 hi/lo ----------------------- */
__global__ __launch_bounds__(256) void convert_feat_kernel(
    const float* __restrict__ feat) {
    size_t i = ((size_t)blockIdx.x * 256 + threadIdx.x) * 4;
    float4 v = *(const float4*)(feat + i);
    __half hx = __float2half_rn(v.x), hy = __float2half_rn(v.y);
    __half hz = __float2half_rn(v.z), hw = __float2half_rn(v.w);
    *(__half2*)(g_Ahi + i) = __halves2half2(hx, hy);
    *(__half2*)(g_Ahi + i + 2) = __halves2half2(hz, hw);
    *(__half2*)(g_Alo + i) = __halves2half2(
        __float2half_rn((v.x - __half2float(hx)) * LO_SCALE),
        __float2half_rn((v.y - __half2float(hy)) * LO_SCALE));
    *(__half2*)(g_Alo + i + 2) = __halves2half2(
        __float2half_rn((v.z - __half2float(hz)) * LO_SCALE),
        __float2half_rn((v.w - __half2float(hw)) * LO_SCALE));
}

/* ------------------- weight transpose+split: [9216,512] -> [512,9216] ----- */
__global__ __launch_bounds__(256) void convert_w_kernel(const float* __restrict__ W) {
    __shared__ float t[32][33];
    const int kb = blockIdx.x * 32, cb = blockIdx.y * 32;
    const int tx = threadIdx.x, ty = threadIdx.y;   /* 32 x 8 */
#pragma unroll
    for (int r = ty; r < 32; r += 8)
        t[r][tx] = W[(size_t)(kb + r) * CMID + cb + tx];
    __syncthreads();
#pragma unroll
    for (int r = ty; r < 32; r += 8) {
        float v = t[tx][r];
        __half h = __float2half_rn(v);
        size_t o = (size_t)(cb + r) * KTOT + kb + tx;
        g_Bhi[o] = h;
        g_Blo[o] = __float2half_rn((v - __half2float(h)) * LO_SCALE);
    }
}

/* ------------------- conv as HMMA fp16-split GEMM ------------------------- */
/* D = A_hi*B_hi + (A_hi*B_lo' + A_lo'*B_hi) * 2^-11, lo' = (x-hi)*2^11.      */
/* Single barrier per K-chunk; ldmatrix fragment loads.                       */
__global__ __launch_bounds__(256, 1) void conv_mma_kernel(
    const float* __restrict__ bias) {
    extern __shared__ __half smh[];
    const uint32_t smb = smem_u32(smh);
    const int tid = threadIdx.x;
    const int wid = tid >> 5, lane = tid & 31;
    const int m0 = blockIdx.x * TM;   /* 118 m-tiles */
    const int n0 = blockIdx.y * TN;   /* 8 n-tiles */
    const int wm = wid >> 1, wn = wid & 1;
    const int r = lane >> 2, cp2 = (lane & 3) * 2;

    /* A loader: 1 row, 32 contiguous halves (4 uint4) per thread, per matrix */
    const int arow = tid >> 1;
    const int c32a = (tid & 1) * 32;
    const int pA = m0 + arow;
    const int apy = pA / FW;
    const int apx = pA - apy * FW;
    const int aok = (pA < NPIX);
    /* B loader: 1 row, 16 halves (2 uint4) per thread per matrix */
    const int brow = tid >> 2;
    const int c16b = (tid & 3) * 16;
    const __half* bsrc_hi = g_Bhi + (size_t)(n0 + brow) * KTOT + c16b;
    const __half* bsrc_lo = g_Blo + (size_t)(n0 + brow) * KTOT + c16b;

    /* ldmatrix lane-address components (halves), validated in round 8 */
    const uint32_t a_lm_row = (uint32_t)(wm * 32 + (lane & 15)) * ASTR +
                              (lane >> 4) * 8;
    const uint32_t b_lm_row =
        (uint32_t)(wn * 32 + (lane & 7) + ((lane >> 4) & 1) * 8) * ASTR +
        ((lane >> 3) & 1) * 8;

    float acc0[2][4][4], acc1[2][4][4];
#pragma unroll
    for (int i = 0; i < 2; i++)
#pragma unroll
        for (int j = 0; j < 4; j++)
#pragma unroll
            for (int k = 0; k < 4; k++) { acc0[i][j][k] = 0.f; acc1[i][j][k] = 0.f; }

    uint4 hA[4], lA[4], hB[2], lB[2];

#define LOAD_CHUNK(c_)                                                        \
    do {                                                                      \
        const int tap_ = (c_) >> 4;                                           \
        const int ci0_ = ((c_) & 15) * KC;                                    \
        const int dy_ = tap_ / 3 - 1, dx_ = tap_ % 3 - 1;                     \
        const int yy = apy + dy_, xx = apx + dx_;                             \
        if (aok && (unsigned)yy < FH && (unsigned)xx < FW) {                  \
            const __half* s =                                                 \
                g_Ahi + (((size_t)(yy * FW + xx)) << 10) + ci0_ + c32a;       \
            const __half* s2 =                                                \
                g_Alo + (((size_t)(yy * FW + xx)) << 10) + ci0_ + c32a;       \
            _Pragma("unroll") for (int q = 0; q < 4; q++) {                   \
                hA[q] = *(const uint4*)(s + q * 8);                           \
                lA[q] = *(const uint4*)(s2 + q * 8);                          \
            }                                                                 \
        } else {                                                              \
            _Pragma("unroll") for (int q = 0; q < 4; q++) {                   \
                hA[q] = make_uint4(0, 0, 0, 0); lA[q] = hA[q];                \
            }                                                                 \
        }                                                                     \
        _Pragma("unroll") for (int q = 0; q < 2; q++) {                       \
            hB[q] = *(const uint4*)(bsrc_hi + (size_t)(c_) * KC + q * 8);     \
            lB[q] = *(const uint4*)(bsrc_lo + (size_t)(c_) * KC + q * 8);     \
        }                                                                     \
    } while (0)

#define STORE_STAGE(buf_)                                                     \
    do {                                                                      \
        __half* bse = smh + (buf_) * STAGE_H;                                 \
        _Pragma("unroll") for (int q = 0; q < 4; q++) {                       \
            *(uint4*)(bse + AHI_O + arow * ASTR + c32a + q * 8) = hA[q];      \
            *(uint4*)(bse + ALO_O + arow * ASTR + c32a + q * 8) = lA[q];      \
        }                                                                     \
        _Pragma("unroll") for (int q = 0; q < 2; q++) {                       \
            *(uint4*)(bse + BHI_O + brow * ASTR + c16b + q * 8) = hB[q];      \
            *(uint4*)(bse + BLO_O + brow * ASTR + c16b + q * 8) = lB[q];      \
        }                                                                     \
    } while (0)

    LOAD_CHUNK(0);
    STORE_STAGE(0);
    LOAD_CHUNK(1);
    __syncthreads();

    for (int c = 0; c < NC; c++) {
        const int buf = c & 1;
        /* stores for chunk c+1 go to buf^1: all readers of buf^1 finished at
           the barrier that ended iteration c-1; compute below reads buf. */
        if (c + 1 < NC) STORE_STAGE(buf ^ 1);
        if (c + 2 < NC) LOAD_CHUNK(c + 2);

        const uint32_t bstg = smb + buf * (STAGE_H * 2);
#pragma unroll
        for (int ks = 0; ks < 4; ks++) {
            uint32_t ah[2][4], al[2][4];
#pragma unroll
            for (int mt = 0; mt < 2; mt++) {
                uint32_t addr = bstg + AHI_O * 2 +
                                (a_lm_row + mt * 16 * ASTR + ks * 16) * 2;
                ldsm4(ah[mt], addr);
                ldsm4(al[mt], addr + (ALO_O - AHI_O) * 2);
            }
            uint32_t bh[4][2], bl[4][2];
#pragma unroll
            for (int pr = 0; pr < 2; pr++) {
                uint32_t addr = bstg + BHI_O * 2 +
                                (b_lm_row + pr * 16 * ASTR + ks * 16) * 2;
                uint32_t t4[4];
                ldsm4(t4, addr);
                bh[pr * 2][0] = t4[0]; bh[pr * 2][1] = t4[1];
                bh[pr * 2 + 1][0] = t4[2]; bh[pr * 2 + 1][1] = t4[3];
                ldsm4(t4, addr + (BLO_O - BHI_O) * 2);
                bl[pr * 2][0] = t4[0]; bl[pr * 2][1] = t4[1];
                bl[pr * 2 + 1][0] = t4[2]; bl[pr * 2 + 1][1] = t4[3];
            }
#pragma unroll
            for (int nt = 0; nt < 4; nt++) {
#pragma unroll
                for (int mt = 0; mt < 2; mt++) {
                    MMA(acc0[mt][nt], ah[mt], bh[nt][0], bh[nt][1]);
                    MMA(acc1[mt][nt], ah[mt], bl[nt][0], bl[nt][1]);
                    MMA(acc1[mt][nt], al[mt], bh[nt][0], bh[nt][1]);
                }
            }
        }
        __syncthreads();
    }

    /* epilogue: combine, bias, relu, store */
#pragma unroll
    for (int mt = 0; mt < 2; mt++) {
#pragma unroll
        for (int nt = 0; nt < 4; nt++) {
            const int n = n0 + wn * 32 + nt * 8 + cp2;
            const float b0v = bias[n], b1v = bias[n + 1];
            const int mA = m0 + wm * 32 + mt * 16 + r;
            const int mB = mA + 8;
            float v0 = acc0[mt][nt][0] + acc1[mt][nt][0] * LO_INV + b0v;
            float v1 = acc0[mt][nt][1] + acc1[mt][nt][1] * LO_INV + b1v;
            float v2 = acc0[mt][nt][2] + acc1[mt][nt][2] * LO_INV + b0v;
            float v3 = acc0[mt][nt][3] + acc1[mt][nt][3] * LO_INV + b1v;
            if (mA < NPIX) {
                g_rpn[(size_t)mA * CMID + n] = fmaxf(v0, 0.f);
                g_rpn[(size_t)mA * CMID + n + 1] = fmaxf(v1, 0.f);
            }
            if (mB < NPIX) {
                g_rpn[(size_t)mB * CMID + n] = fmaxf(v2, 0.f);
                g_rpn[(size_t)mB * CMID + n + 1] = fmaxf(v3, 0.f);
            }
        }
    }
}

/* ------------------- 1x1 heads + softmax + box decode --------------------- */
__global__ __launch_bounds__(64) void head_decode_kernel(
    const float* __restrict__ Ws, const float* __restrict__ bs,
    const float* __restrict__ Wb, const float* __restrict__ bb,
    const int* __restrict__ img) {
    const int ppix = blockIdx.x;
    __shared__ float s[CMID];
    __shared__ float outv[54];
    const int t = threadIdx.x;

    for (int i = t; i < CMID; i += 64) s[i] = g_rpn[(size_t)ppix * CMID + i];
    __syncthreads();

    if (t < 54) {
        const bool isc = (t < 18);
        const float* Wp = isc ? Ws : Wb;
        const int co = isc ? t : (t - 18);
        const int stride = isc ? 18 : 36;
        float a0 = 0.f, a1 = 0.f, a2 = 0.f, a3 = 0.f;
        for (int c = 0; c < CMID; c += 4) {
            a0 += s[c + 0] * Wp[(c + 0) * stride + co];
            a1 += s[c + 1] * Wp[(c + 1) * stride + co];
            a2 += s[c + 2] * Wp[(c + 2) * stride + co];
            a3 += s[c + 3] * Wp[(c + 3) * stride + co];
        }
        outv[t] = (isc ? bs[t] : bb[t - 18]) + ((a0 + a1) + (a2 + a3));
    }
    __syncthreads();

    if (t < 9) {
        const float l0 = outv[t * 2 + 0], l1 = outv[t * 2 + 1];
        const float mx = fmaxf(l0, l1);
        const float e0 = expf(l0 - mx), e1 = expf(l1 - mx);
        float fg = e1 / (e0 + e1);

        const float dx = outv[18 + t * 4 + 0];
        const float dy = outv[18 + t * 4 + 1];
        const float dw = outv[18 + t * 4 + 2];
        const float dh = outv[18 + t * 4 + 3];

        const int y = ppix / FW, x = ppix % FW;
        const float sx = (float)(x * 16), sy = (float)(y * 16);
        const float ax1 = sx + c_anch[t][0];
        const float ay1 = sy + c_anch[t][1];
        const float ax2 = sx + c_anch[t][2];
        const float ay2 = sy + c_anch[t][3];
        const float aw = ax2 - ax1 + 1.f;
        const float ah = ay2 - ay1 + 1.f;
        const float acx = ax1 + 0.5f * aw;
        const float acy = ay1 + 0.5f * ah;
        const float pcx = dx * aw + acx;
        const float pcy = dy * ah + acy;
        const float pw = expf(dw) * aw;
        const float ph = expf(dh) * ah;
        const float imh = (float)img[0];
        const float imw = (float)img[1];
        float x1 = fminf(fmaxf(pcx - 0.5f * pw, 0.f), imw - 1.f);
        float y1 = fminf(fmaxf(pcy - 0.5f * ph, 0.f), imh - 1.f);
        float x2 = fminf(fmaxf(pcx + 0.5f * pw, 0.f), imw - 1.f);
        float y2 = fminf(fmaxf(pcy + 0.5f * ph, 0.f), imh - 1.f);
        const float bw = x2 - x1 + 1.f;
        const float bh = y2 - y1 + 1.f;
        if (!(bw >= 16.f && bh >= 16.f)) fg = NEG_BIG;

        const int idx = ppix * 9 + t;
        g_scores[idx] = fg;
        g_boxes[idx * 4 + 0] = x1;
        g_boxes[idx * 4 + 1] = y1;
        g_boxes[idx * 4 + 2] = x2;
        g_boxes[idx * 4 + 3] = y2;
    }
}

/* ------------------- top-6000 selection ----------------------------------- */
__global__ void zero_aux_kernel() {
    int i = blockIdx.x * blockDim.x + threadIdx.x;
    if (i < HSIZE) g_hist[i] = 0;
    if (i < CAND_CAP) g_cand[i] = 0ull;
    if (i == 0) g_cand_cnt = 0;
}

__global__ void hist_kernel() {
    int i = blockIdx.x * blockDim.x + threadIdx.x;
    if (i < NANCH) {
        unsigned key = fkey(g_scores[i]);
        atomicAdd(&g_hist[key >> (32 - HBITS)], 1u);
    }
}

__global__ void find_thresh_kernel() {
    __shared__ unsigned csum[1024];
    const int t = threadIdx.x;
    const int chunk = HSIZE / 1024; /* 256 */
    unsigned s = 0;
    const int base = t * chunk;
    for (int i = 0; i < chunk; i++) s += g_hist[base + i];
    csum[t] = s;
    __syncthreads();
    if (t == 0) {
        unsigned cum = 0;
        int c = 1023;
        for (; c >= 0; c--) {
            if (cum + csum[c] >= (unsigned)PRE_NMS) break;
            cum += csum[c];
        }
        int B = 0;
        if (c >= 0) {
            for (int b = c * chunk + chunk - 1; b >= c * chunk; b--) {
                cum += g_hist[b];
                if (cum >= (unsigned)PRE_NMS) { B = b; break; }
            }
        }
        g_thresh_bin = B;
    }
}

__global__ void compact_kernel() {
    int i = blockIdx.x * blockDim.x + threadIdx.x;
    if (i < NANCH) {
        unsigned key = fkey(g_scores[i]);
        if ((int)(key >> (32 - HBITS)) >= g_thresh_bin) {
            int pos = atomicAdd(&g_cand_cnt, 1);
            if (pos < CAND_CAP)
                g_cand[pos] = ((unsigned long long)key << 32) |
                              (unsigned)(~(unsigned)i);
        }
    }
}

/* single-block bitonic sort of 8192 64-bit keys, descending.
   key = flip(score)<<32 | ~idx  ->  stable top-k identical to lax.top_k. */
__global__ void sort_kernel() {
    extern __shared__ unsigned long long sk[];
    const int t = threadIdx.x;
    for (int i = t; i < CAND_CAP; i += 1024) sk[i] = g_cand[i];
    __syncthreads();
    for (int k = 2; k <= CAND_CAP; k <<= 1) {
        for (int j = k >> 1; j > 0; j >>= 1) {
            for (int i = t; i < CAND_CAP; i += 1024) {
                int l = i ^ j;
                if (l > i) {
                    bool desc = ((i & k) == 0);
                    unsigned long long a = sk[i], b = sk[l];
                    if ((a < b) == desc) { sk[i] = b; sk[l] = a; }
                }
            }
            __syncthreads();
        }
    }
    for (int i = t; i < PRE_NMS; i += 1024) {
        unsigned long long key = sk[i];
        if (key == 0ull) {
            g_top_scores[i] = -2e9f;
            g_top_boxes[i * 4 + 0] = 0.f;
            g_top_boxes[i * 4 + 1] = 0.f;
            g_top_boxes[i * 4 + 2] = 0.f;
            g_top_boxes[i * 4 + 3] = 0.f;
            continue;
        }
        unsigned idx = ~(unsigned)(key & 0xFFFFFFFFull);
        g_top_scores[i] = g_scores[idx];
        g_top_boxes[i * 4 + 0] = g_boxes[idx * 4 + 0];
        g_top_boxes[i * 4 + 1] = g_boxes[idx * 4 + 1];
        g_top_boxes[i * 4 + 2] = g_boxes[idx * 4 + 2];
        g_top_boxes[i * 4 + 3] = g_boxes[idx * 4 + 3];
    }
}

/* ------------------- NMS ---------------------------------------------------*/
__global__ __launch_bounds__(64) void nms_mask_kernel() {
    const int cb = blockIdx.x, rb = blockIdx.y;
    __shared__ float4 cbox[64];
    const int t = threadIdx.x;
    const int cj = cb * 64 + t;
    if (cj < PRE_NMS) cbox[t] = *(const float4*)&g_top_boxes[cj * 4];
    __syncthreads();
    const int i = rb * 64 + t;
    if (i >= PRE_NMS) return;
    const float4 r = *(const float4*)&g_top_boxes[i * 4];
    const float ra = (r.z - r.x + 1.f) * (r.w - r.y + 1.f);
    const int cc = min(64, PRE_NMS - cb * 64);
    unsigned long long m = 0ull;
    for (int jj = 0; jj < cc; jj++) {
        const float4 c = cbox[jj];
        float iw = fminf(r.z, c.z) - fmaxf(r.x, c.x) + 1.f;
        float ih = fminf(r.w, c.w) - fmaxf(r.y, c.y) + 1.f;
        iw = fmaxf(iw, 0.f);
        ih = fmaxf(ih, 0.f);
        const float inter = iw * ih;
        const float ca = (c.z - c.x + 1.f) * (c.w - c.y + 1.f);
        const float iou = inter / (ra + ca - inter);
        if (iou > 0.7f) m |= (1ull << jj);
    }
    g_mask[(size_t)i * NBLK + cb] = m;
}

__global__ __launch_bounds__(128) void nms_reduce_kernel(float* __restrict__ out) {
    __shared__ unsigned long long remv[NBLK];
    __shared__ int cnt;
    const int t = threadIdx.x;
    if (t < NBLK) remv[t] = 0ull;
    if (t == 0) cnt = 0;
    for (int i = t; i < POST_NMS * 4; i += 128) out[i] = 0.f;
    __syncthreads();
    for (int i = 0; i < PRE_NMS; i++) {
        const bool keep = !((remv[i >> 6] >> (i & 63)) & 1ull);
        if (keep) {
            if (t < NBLK) remv[t] |= g_mask[(size_t)i * NBLK + t];
            if (t == 0 && g_top_scores[i] > -100000000.0f) {
                const int c = cnt;
                out[c * 4 + 0] = g_top_boxes[i * 4 + 0];
                out[c * 4 + 1] = g_top_boxes[i * 4 + 1];
                out[c * 4 + 2] = g_top_boxes[i * 4 + 2];
                out[c * 4 + 3] = g_top_boxes[i * 4 + 3];
                cnt = c + 1;
            }
            __syncthreads();
            if (cnt >= POST_NMS) break;
        }
    }
}

/* ------------------- launch ------------------------------------------------*/
extern "C" void kernel_launch(void* const* d_in, const int* in_sizes, int n_in,
                              void* d_out, int out_size) {
    const float* feat = (const float*)d_in[0];
    const float* Wr   = (const float*)d_in[1];
    const float* br   = (const float*)d_in[2];
    const float* Ws   = (const float*)d_in[3];
    const float* bs   = (const float*)d_in[4];
    const float* Wb   = (const float*)d_in[5];
    const float* bb   = (const float*)d_in[6];
    const int*   img  = (const int*)d_in[7];
    float* out = (float*)d_out;

    convert_feat_kernel<<<NPIX, 256>>>(feat);
    convert_w_kernel<<<dim3(KTOT / 32, CMID / 32), dim3(32, 8)>>>(Wr);

    cudaFuncSetAttribute(conv_mma_kernel,
                         cudaFuncAttributeMaxDynamicSharedMemorySize,
                         SMEM_CONV_TOTAL);
    conv_mma_kernel<<<dim3(118, CMID / TN), 256, SMEM_CONV_TOTAL>>>(br);

    head_decode_kernel<<<NPIX, 64>>>(Ws, bs, Wb, bb, img);
    zero_aux_kernel<<<HSIZE / 256, 256>>>();
    hist_kernel<<<(NANCH + 255) / 256, 256>>>();
    find_thresh_kernel<<<1, 1024>>>();
    compact_kernel<<<(NANCH + 255) / 256, 256>>>();
    cudaFuncSetAttribute(sort_kernel,
                         cudaFuncAttributeMaxDynamicSharedMemorySize, 65536);
    sort_kernel<<<1, 1024, 65536>>>();
    nms_mask_kernel<<<dim3(NBLK, NBLK), 64>>>();
    nms_reduce_kernel<<<1, 128>>>(out);
}